// round 2
// baseline (speedup 1.0000x reference)
#include <cuda_runtime.h>
#include <math.h>

// Problem constants (fixed by the reference setup)
#define BATCH   16
#define NANCH   36864      // 64*64*9
#define TPB     1024
#define ITEMS   36         // NANCH / TPB
#define TOPN    300
#define NGT     64
#define NPOS    64
#define NEGINF  (-1e30f)

// Scratch (static device allocation — no runtime alloc)
__device__ float4 g_boxes[BATCH * NANCH];   // decoded (unclipped) boxes
__device__ float4 g_nms[BATCH * TOPN];      // NMS output, clipped, zeros when invalid

// ---------------------------------------------------------------------------
// Kernel 1: decode deltas -> boxes (mirrors reference op order exactly)
// ---------------------------------------------------------------------------
__global__ void decode_kernel(const float4* __restrict__ deltas,
                              const float4* __restrict__ anchors) {
    int i = blockIdx.x * blockDim.x + threadIdx.x;
    if (i >= BATCH * NANCH) return;
    float4 a = anchors[i];
    float4 d = deltas[i];
    float ah  = a.z - a.x;
    float aw  = a.w - a.y;
    float acy = a.x + 0.5f * ah;
    float acx = a.y + 0.5f * aw;
    float h   = expf(d.z) * ah;
    float w   = expf(d.w) * aw;
    float cy  = d.x * ah + acy;
    float cx  = d.y * aw + acx;
    float y1  = cy - 0.5f * h;
    float x1  = cx - 0.5f * w;
    g_boxes[i] = make_float4(y1, x1, y1 + h, x1 + w);
}

// ---------------------------------------------------------------------------
// Kernel 2: sequential greedy NMS, one CTA per batch.
// Per-thread: 36 strided elements; active bitmask in regs; cached local max
// (valid until one of *my* elements gets suppressed) -> rescan-on-demand.
// ---------------------------------------------------------------------------
__global__ __launch_bounds__(TPB, 1)
void nms_kernel(const float* __restrict__ labels) {
    __shared__ float sVal[32];
    __shared__ int   sIdx[32];
    __shared__ float sBV;
    __shared__ int   sBI;
    extern __shared__ float scores[];   // NANCH floats; each entry touched by its owner thread only

    const int b = blockIdx.x;
    const int t = threadIdx.x;
    const float*  sc    = labels  + (size_t)b * NANCH;
    const float4* boxes = g_boxes + (size_t)b * NANCH;

    unsigned long long act = (1ull << ITEMS) - 1ull;

    // initial load + cached local max (ascending e -> first-max = lowest index)
    float cv = -INFINITY; int ci = 0x7FFFFFFF;
    #pragma unroll
    for (int k = 0; k < ITEMS; k++) {
        int e = k * TPB + t;
        float v = sc[e];
        scores[e] = v;
        if (v > cv) { cv = v; ci = e; }
    }

    int iter = 0;
    for (; iter < TOPN; iter++) {
        // ---- block argmax over cached per-thread maxima (tie: lowest index) ----
        float v = cv; int ix = ci;
        #pragma unroll
        for (int off = 16; off > 0; off >>= 1) {
            float v2 = __shfl_down_sync(0xFFFFFFFFu, v, off);
            int   i2 = __shfl_down_sync(0xFFFFFFFFu, ix, off);
            if (v2 > v || (v2 == v && i2 < ix)) { v = v2; ix = i2; }
        }
        if ((t & 31) == 0) { sVal[t >> 5] = v; sIdx[t >> 5] = ix; }
        __syncthreads();
        if (t < 32) {
            v = sVal[t]; ix = sIdx[t];
            #pragma unroll
            for (int off = 16; off > 0; off >>= 1) {
                float v2 = __shfl_down_sync(0xFFFFFFFFu, v, off);
                int   i2 = __shfl_down_sync(0xFFFFFFFFu, ix, off);
                if (v2 > v || (v2 == v && i2 < ix)) { v = v2; ix = i2; }
            }
            if (t == 0) { sBV = v; sBI = ix; }
        }
        __syncthreads();
        float bv = sBV;
        int   bi = sBI;
        if (!(bv > NEGINF * 0.5f)) break;   // valid==false: all remaining slots zero

        float4 sb = __ldg(&boxes[bi]);      // uniform address: broadcast load
        if (t == 0) {
            float4 c;
            c.x = fminf(fmaxf(sb.x, 0.0f), 1.0f);
            c.y = fminf(fmaxf(sb.y, 0.0f), 1.0f);
            c.z = fminf(fmaxf(sb.z, 0.0f), 1.0f);
            c.w = fminf(fmaxf(sb.w, 0.0f), 1.0f);
            g_nms[b * TOPN + iter] = c;
        }

        // winner's owner drops it
        if ((bi & (TPB - 1)) == t) act &= ~(1ull << (bi >> 10));
        bool rescan = (bi == ci);

        float sah   = sb.z - sb.x;
        float saw   = sb.w - sb.y;
        float areaS = sah * saw;

        // ---- suppress: active elements only (uniform loop, predicated body) ----
        #pragma unroll 4
        for (int k = 0; k < ITEMS; k++) {
            if (!((act >> k) & 1ull)) continue;
            int e = k * TPB + t;
            float4 bb = __ldg(&boxes[e]);
            float yy1 = fmaxf(sb.x, bb.x);
            float xx1 = fmaxf(sb.y, bb.y);
            float yy2 = fminf(sb.z, bb.z);
            float xx2 = fminf(sb.w, bb.w);
            float ih  = fmaxf(yy2 - yy1, 0.0f);
            float iw  = fmaxf(xx2 - xx1, 0.0f);
            float inter = ih * iw;
            float areaB = (bb.z - bb.x) * (bb.w - bb.y);
            float iou   = inter / (((areaS + areaB) - inter) + 1e-7f);
            if (iou >= 0.5f) {
                act &= ~(1ull << k);
                if (e == ci) rescan = true;
            }
        }

        // ---- rescan own actives only when the cached max was killed ----
        if (rescan) {
            cv = -INFINITY; ci = 0x7FFFFFFF;
            #pragma unroll 4
            for (int k = 0; k < ITEMS; k++) {
                if (!((act >> k) & 1ull)) continue;
                int e = k * TPB + t;
                float v2 = scores[e];
                if (v2 > cv) { cv = v2; ci = e; }
            }
        }
    }

    // zero-fill remaining (invalid) slots
    for (int s = iter + t; s < TOPN; s += TPB)
        g_nms[b * TOPN + s] = make_float4(0.f, 0.f, 0.f, 0.f);
}

// ---------------------------------------------------------------------------
// Kernel 3: IoU vs GT, per-row max/argmax, stable rank-by-counting, write out.
// ---------------------------------------------------------------------------
__global__ void select_kernel(const float4* __restrict__ gt,
                              float* __restrict__ out,
                              int out_size) {
    __shared__ float4 nb[TOPN];
    __shared__ float4 gtb[NGT];
    __shared__ float  merged[TOPN];
    __shared__ int    gbest[TOPN];

    const int b = blockIdx.x;
    const int t = threadIdx.x;   // 512 threads

    if (t < TOPN) nb[t] = g_nms[b * TOPN + t];
    int u = t - TOPN;
    if (u >= 0 && u < NGT) gtb[u] = gt[b * NGT + u];
    __syncthreads();

    if (t < TOPN) {
        float4 A = nb[t];
        float areaA = (A.z - A.x) * (A.w - A.y);
        float best = -INFINITY; int bj = 0;
        #pragma unroll 4
        for (int j = 0; j < NGT; j++) {
            float4 G = gtb[j];
            float yy1 = fmaxf(A.x, G.x);
            float xx1 = fmaxf(A.y, G.y);
            float yy2 = fminf(A.z, G.z);
            float xx2 = fminf(A.w, G.w);
            float ih  = fmaxf(yy2 - yy1, 0.0f);
            float iw  = fmaxf(xx2 - xx1, 0.0f);
            float inter = ih * iw;
            float areaG = (G.z - G.x) * (G.w - G.y);
            float iou   = inter / (((areaA + areaG) - inter) + 1e-7f);
            if (iou > best) { best = iou; bj = j; }   // strict > == first occurrence
        }
        merged[t] = best;
        gbest[t]  = bj;
    }
    __syncthreads();

    if (t < TOPN) {
        float mv = merged[t];
        int rank = 0;
        for (int q = 0; q < TOPN; q++) {
            float qv = merged[q];
            rank += (qv > mv) || (qv == mv && q < t);   // stable: matches jnp.argsort
        }
        if (rank < NPOS) {
            float4 A = nb[t];
            float* o = out + (size_t)b * 512 + (size_t)rank * 4;
            o[0] = A.x; o[1] = A.y; o[2] = A.z; o[3] = A.w;
            if (out_size >= BATCH * 512 + BATCH * NGT) {
                out[BATCH * 512 + b * NGT + rank] = (float)gbest[t];
            }
        }
    }

    // negatives: rows 64..127 are zeros
    for (int i = t; i < 256; i += blockDim.x)
        out[(size_t)b * 512 + 256 + i] = 0.0f;
}

// ---------------------------------------------------------------------------
extern "C" void kernel_launch(void* const* d_in, const int* in_sizes, int n_in,
                              void* d_out, int out_size) {
    const float4* deltas  = (const float4*)d_in[0];  // (B,64,64,36)
    const float*  labels  = (const float*)d_in[1];   // (B,64,64,9)
    const float4* anchors = (const float4*)d_in[2];  // (B,N,4)
    const float4* gt      = (const float4*)d_in[3];  // (B,64,4)
    float* out = (float*)d_out;

    (void)in_sizes; (void)n_in;

    static_assert(ITEMS * TPB == NANCH, "tiling must cover N exactly");

    size_t smem = (size_t)NANCH * sizeof(float);
    cudaFuncSetAttribute(nms_kernel, cudaFuncAttributeMaxDynamicSharedMemorySize, (int)smem);

    decode_kernel<<<(BATCH * NANCH + 255) / 256, 256>>>(deltas, anchors);
    nms_kernel<<<BATCH, TPB, smem>>>(labels);
    select_kernel<<<BATCH, 512>>>(gt, out, out_size);
}

// round 3
// speedup vs baseline: 8.3578x; 8.3578x over previous
#include <cuda_runtime.h>
#include <math.h>

// Problem constants (fixed by the reference setup)
#define BATCH   16
#define NANCH   36864      // 64*64*9
#define TPB     1024
#define SEG     36         // NANCH / TPB (items per thread in sort)
#define TOPN    300
#define NGT     64
#define NPOS    64

// Scratch (static device allocations — no runtime alloc)
__device__ float4 g_boxes[BATCH * NANCH];                   // decoded (unclipped) boxes
__device__ float4 g_nms[BATCH * TOPN];                      // NMS output, clipped, zeros when invalid
__device__ unsigned long long g_items0[BATCH * NANCH];      // radix ping
__device__ unsigned long long g_items1[BATCH * NANCH];      // radix pong

// ---------------------------------------------------------------------------
// IoU exactly as reference: inter / (((areaA + areaB) - inter) + 1e-7)
// ---------------------------------------------------------------------------
__device__ __forceinline__ float iou_ref(float4 a, float4 b) {
    float yy1 = fmaxf(a.x, b.x);
    float xx1 = fmaxf(a.y, b.y);
    float yy2 = fminf(a.z, b.z);
    float xx2 = fminf(a.w, b.w);
    float ih  = fmaxf(yy2 - yy1, 0.0f);
    float iw  = fmaxf(xx2 - xx1, 0.0f);
    float inter = ih * iw;
    float areaA = (a.z - a.x) * (a.w - a.y);
    float areaB = (b.z - b.x) * (b.w - b.y);
    return inter / (((areaA + areaB) - inter) + 1e-7f);
}

// ---------------------------------------------------------------------------
// Kernel 1: decode deltas -> boxes (mirrors reference op order exactly)
// ---------------------------------------------------------------------------
__global__ void decode_kernel(const float4* __restrict__ deltas,
                              const float4* __restrict__ anchors) {
    int i = blockIdx.x * blockDim.x + threadIdx.x;
    if (i >= BATCH * NANCH) return;
    float4 a = anchors[i];
    float4 d = deltas[i];
    float ah  = a.z - a.x;
    float aw  = a.w - a.y;
    float acy = a.x + 0.5f * ah;
    float acx = a.y + 0.5f * aw;
    float h   = expf(d.z) * ah;
    float w   = expf(d.w) * aw;
    float cy  = d.x * ah + acy;
    float cx  = d.y * aw + acx;
    float y1  = cy - 0.5f * h;
    float x1  = cx - 0.5f * w;
    g_boxes[i] = make_float4(y1, x1, y1 + h, x1 + w);
}

// ---------------------------------------------------------------------------
// Kernel 2: sort-then-scan NMS, one CTA of 1024 threads per batch.
//   Stage A: LSD radix sort (8 passes x 4 bits) of (~score_bits, index),
//            ascending on complemented bits == descending score, stable
//            (ties -> lowest original index first, matching argmax).
//   Stage B: walk sorted order in 1024-box chunks; a box is kept iff
//            IoU < 0.5 vs every previously kept box. First-alive in a
//            sorted chunk == global argmax of remaining.
// ---------------------------------------------------------------------------
__global__ __launch_bounds__(TPB, 1)
void nms_kernel(const float* __restrict__ labels) {
    extern __shared__ unsigned int sCounts[];   // 16 * 1024 u32 = 64 KB
    __shared__ float4       sChunk[TPB];        // 16 KB
    __shared__ float4       sKept[TOPN];        // 4.8 KB (unclipped)
    __shared__ int          sWarpCand[32];
    __shared__ unsigned int sWarpSum[32];
    __shared__ int          sWinner;

    const int b    = blockIdx.x;
    const int t    = threadIdx.x;
    const int lane = t & 31;
    const int warp = t >> 5;

    const float*  sc    = labels  + (size_t)b * NANCH;
    const float4* boxes = g_boxes + (size_t)b * NANCH;
    unsigned long long* bufA = g_items0 + (size_t)b * NANCH;
    unsigned long long* bufB = g_items1 + (size_t)b * NANCH;

    // ---------------- build items: (~score_bits)<<32 | index ----------------
    #pragma unroll
    for (int k = 0; k < SEG; k++) {
        int e = k * TPB + t;                       // coalesced
        unsigned int ck = ~__float_as_uint(sc[e]); // scores >= 0 -> monotonic bits
        bufA[e] = ((unsigned long long)ck << 32) | (unsigned int)e;
    }
    __syncthreads();

    // ---------------- 8-pass 4-bit LSD radix (stable) ----------------
    for (int p = 0; p < 8; p++) {
        unsigned long long* src = (p & 1) ? bufB : bufA;
        unsigned long long* dst = (p & 1) ? bufA : bufB;
        const int sh = 32 + 4 * p;

        // zero counts
        #pragma unroll
        for (int i = 0; i < 16; i++) sCounts[t * 16 + i] = 0u;
        __syncthreads();

        // phase 1: histogram (thread t owns contiguous segment [t*SEG, t*SEG+SEG))
        #pragma unroll
        for (int i = 0; i < SEG; i++) {
            unsigned long long it = src[t * SEG + i];
            unsigned int d = (unsigned int)(it >> sh) & 15u;
            sCounts[d * TPB + t]++;                // stride 1024 -> conflict-free
        }
        __syncthreads();

        // phase 2: exclusive prefix over flat sCounts[16384], order = d*1024 + t
        unsigned int v[16], run = 0;
        #pragma unroll
        for (int i = 0; i < 16; i++) {
            unsigned int x = sCounts[t * 16 + i];
            v[i] = run; run += x;
        }
        // block exclusive scan of per-thread totals
        unsigned int x = run;
        #pragma unroll
        for (int off = 1; off < 32; off <<= 1) {
            unsigned int y = __shfl_up_sync(0xFFFFFFFFu, x, off);
            if (lane >= off) x += y;
        }
        if (lane == 31) sWarpSum[warp] = x;
        __syncthreads();
        if (warp == 0) {
            unsigned int s = sWarpSum[lane];
            #pragma unroll
            for (int off = 1; off < 32; off <<= 1) {
                unsigned int y = __shfl_up_sync(0xFFFFFFFFu, s, off);
                if (lane >= off) s += y;
            }
            sWarpSum[lane] = s;                    // inclusive warp totals
        }
        __syncthreads();
        unsigned int warpOff = (warp == 0) ? 0u : sWarpSum[warp - 1];
        unsigned int myExcl  = warpOff + x - run;  // exclusive offset of this thread's 16-group
        #pragma unroll
        for (int i = 0; i < 16; i++) sCounts[t * 16 + i] = v[i] + myExcl;
        __syncthreads();

        // phase 3: stable scatter
        #pragma unroll
        for (int i = 0; i < SEG; i++) {
            unsigned long long it = src[t * SEG + i];
            unsigned int d = (unsigned int)(it >> sh) & 15u;
            unsigned int pos = sCounts[d * TPB + t]++;
            dst[pos] = it;
        }
        __syncthreads();
    }
    // after 8 passes sorted data is back in bufA

    // ---------------- chunked greedy scan ----------------
    int kc = 0;
    for (int base = 0; base < NANCH && kc < TOPN; base += TPB) {
        // load chunk + prefilter against already-kept boxes
        unsigned long long it = bufA[base + t];
        int e = (int)(it & 0xFFFFFFFFu);
        float4 myBox = boxes[e];
        sChunk[t] = myBox;
        bool alive = true;
        for (int j = 0; j < kc; j++) {
            if (iou_ref(sKept[j], myBox) >= 0.5f) { alive = false; break; }
        }
        __syncthreads();

        // pick loop: first alive slot == argmax of all remaining boxes
        while (kc < TOPN) {
            unsigned int bal = __ballot_sync(0xFFFFFFFFu, alive);
            if (lane == 0) sWarpCand[warp] = bal ? (warp * 32 + __ffs(bal) - 1) : 0x7FFFFFFF;
            __syncthreads();
            if (t < 32) {
                int c = sWarpCand[t];
                #pragma unroll
                for (int off = 16; off > 0; off >>= 1)
                    c = min(c, __shfl_down_sync(0xFFFFFFFFu, c, off));
                if (t == 0) sWinner = c;
            }
            __syncthreads();
            int w = sWinner;
            if (w == 0x7FFFFFFF) break;            // chunk exhausted

            float4 wb = sChunk[w];                 // broadcast read
            if (t == 0) {
                sKept[kc] = wb;                    // unclipped, for suppression
                float4 c;
                c.x = fminf(fmaxf(wb.x, 0.0f), 1.0f);
                c.y = fminf(fmaxf(wb.y, 0.0f), 1.0f);
                c.z = fminf(fmaxf(wb.z, 0.0f), 1.0f);
                c.w = fminf(fmaxf(wb.w, 0.0f), 1.0f);
                g_nms[b * TOPN + kc] = c;
            }
            if (alive) {
                if (t == w)                         alive = false;  // explicit self-suppress
                else if (iou_ref(wb, myBox) >= 0.5f) alive = false;
            }
            kc++;
            __syncthreads();
        }
    }

    // zero-fill remaining (invalid) slots
    for (int s = kc + t; s < TOPN; s += TPB)
        g_nms[b * TOPN + s] = make_float4(0.f, 0.f, 0.f, 0.f);
}

// ---------------------------------------------------------------------------
// Kernel 3: IoU vs GT, per-row max/argmax, stable rank-by-counting, write out.
// ---------------------------------------------------------------------------
__global__ void select_kernel(const float4* __restrict__ gt,
                              float* __restrict__ out,
                              int out_size) {
    __shared__ float4 nb[TOPN];
    __shared__ float4 gtb[NGT];
    __shared__ float  merged[TOPN];
    __shared__ int    gbest[TOPN];

    const int b = blockIdx.x;
    const int t = threadIdx.x;   // 512 threads

    if (t < TOPN) nb[t] = g_nms[b * TOPN + t];
    int u = t - TOPN;
    if (u >= 0 && u < NGT) gtb[u] = gt[b * NGT + u];
    __syncthreads();

    if (t < TOPN) {
        float4 A = nb[t];
        float areaA = (A.z - A.x) * (A.w - A.y);
        float best = -INFINITY; int bj = 0;
        #pragma unroll 4
        for (int j = 0; j < NGT; j++) {
            float4 G = gtb[j];
            float yy1 = fmaxf(A.x, G.x);
            float xx1 = fmaxf(A.y, G.y);
            float yy2 = fminf(A.z, G.z);
            float xx2 = fminf(A.w, G.w);
            float ih  = fmaxf(yy2 - yy1, 0.0f);
            float iw  = fmaxf(xx2 - xx1, 0.0f);
            float inter = ih * iw;
            float areaG = (G.z - G.x) * (G.w - G.y);
            float iou   = inter / (((areaA + areaG) - inter) + 1e-7f);
            if (iou > best) { best = iou; bj = j; }   // strict > == first occurrence
        }
        merged[t] = best;
        gbest[t]  = bj;
    }
    __syncthreads();

    if (t < TOPN) {
        float mv = merged[t];
        int rank = 0;
        for (int q = 0; q < TOPN; q++) {
            float qv = merged[q];
            rank += (qv > mv) || (qv == mv && q < t);   // stable: matches jnp.argsort
        }
        if (rank < NPOS) {
            float4 A = nb[t];
            float* o = out + (size_t)b * 512 + (size_t)rank * 4;
            o[0] = A.x; o[1] = A.y; o[2] = A.z; o[3] = A.w;
            if (out_size >= BATCH * 512 + BATCH * NGT) {
                out[BATCH * 512 + b * NGT + rank] = (float)gbest[t];
            }
        }
    }

    // negatives: rows 64..127 are zeros
    for (int i = t; i < 256; i += blockDim.x)
        out[(size_t)b * 512 + 256 + i] = 0.0f;
}

// ---------------------------------------------------------------------------
extern "C" void kernel_launch(void* const* d_in, const int* in_sizes, int n_in,
                              void* d_out, int out_size) {
    const float4* deltas  = (const float4*)d_in[0];  // (B,64,64,36)
    const float*  labels  = (const float*)d_in[1];   // (B,64,64,9)
    const float4* anchors = (const float4*)d_in[2];  // (B,N,4)
    const float4* gt      = (const float4*)d_in[3];  // (B,64,4)
    float* out = (float*)d_out;

    (void)in_sizes; (void)n_in;

    static_assert(SEG * TPB == NANCH, "tiling must cover N exactly");

    size_t smem = 16u * TPB * sizeof(unsigned int);   // 64 KB radix count matrix
    cudaFuncSetAttribute(nms_kernel, cudaFuncAttributeMaxDynamicSharedMemorySize, (int)smem);

    decode_kernel<<<(BATCH * NANCH + 255) / 256, 256>>>(deltas, anchors);
    nms_kernel<<<BATCH, TPB, smem>>>(labels);
    select_kernel<<<BATCH, 512>>>(gt, out, out_size);
}

// round 4
// speedup vs baseline: 15.5629x; 1.8621x over previous
#include <cuda_runtime.h>
#include <math.h>

// Problem constants (fixed by the reference setup)
#define BATCH    16
#define NANCH    36864      // 64*64*9
#define TPB      1024
#define SEG      36         // NANCH / TPB
#define TOPN     300
#define NGT      64
#define NPOS     64
#define NBUCK    8192       // top-13-bit score buckets
#define CAND_MAX 8192       // max candidates per tranche (smem capacity)
#define ITEMC    8          // CAND_MAX / TPB
#define TARGET   4096       // desired candidates in first tranche

typedef unsigned long long u64;
typedef unsigned int u32;

// Scratch (static device allocations — no runtime alloc)
__device__ float4 g_boxes[BATCH * NANCH];   // decoded (unclipped) boxes
__device__ float4 g_nms[BATCH * TOPN];      // NMS output, clipped, zeros when invalid
__device__ u32    g_cum[BATCH * NBUCK];     // inclusive bucket prefix sums

// ---------------------------------------------------------------------------
// IoU exactly as reference: inter / (((areaA + areaB) - inter) + 1e-7)
// ---------------------------------------------------------------------------
__device__ __forceinline__ float iou_ref(float4 a, float4 b) {
    float yy1 = fmaxf(a.x, b.x);
    float xx1 = fmaxf(a.y, b.y);
    float yy2 = fminf(a.z, b.z);
    float xx2 = fminf(a.w, b.w);
    float ih  = fmaxf(yy2 - yy1, 0.0f);
    float iw  = fmaxf(xx2 - xx1, 0.0f);
    float inter = ih * iw;
    float areaA = (a.z - a.x) * (a.w - a.y);
    float areaB = (b.z - b.x) * (b.w - b.y);
    return inter / (((areaA + areaB) - inter) + 1e-7f);
}

// exclusive block scan of per-thread totals (1024 threads, 32 warps)
__device__ __forceinline__ u32 block_excl_scan(u32 run, int lane, int warp, u32* sWarpSum) {
    u32 x = run;
    #pragma unroll
    for (int off = 1; off < 32; off <<= 1) {
        u32 y = __shfl_up_sync(0xFFFFFFFFu, x, off);
        if (lane >= off) x += y;
    }
    if (lane == 31) sWarpSum[warp] = x;
    __syncthreads();
    if (warp == 0) {
        u32 s = sWarpSum[lane];
        #pragma unroll
        for (int off = 1; off < 32; off <<= 1) {
            u32 y = __shfl_up_sync(0xFFFFFFFFu, s, off);
            if (lane >= off) s += y;
        }
        sWarpSum[lane] = s;
    }
    __syncthreads();
    u32 warpOff = (warp == 0) ? 0u : sWarpSum[warp - 1];
    return warpOff + x - run;
}

// ---------------------------------------------------------------------------
// Kernel 1: decode deltas -> boxes (mirrors reference op order exactly)
// ---------------------------------------------------------------------------
__global__ void decode_kernel(const float4* __restrict__ deltas,
                              const float4* __restrict__ anchors) {
    int i = blockIdx.x * blockDim.x + threadIdx.x;
    if (i >= BATCH * NANCH) return;
    float4 a = anchors[i];
    float4 d = deltas[i];
    float ah  = a.z - a.x;
    float aw  = a.w - a.y;
    float acy = a.x + 0.5f * ah;
    float acx = a.y + 0.5f * aw;
    float h   = expf(d.z) * ah;
    float w   = expf(d.w) * aw;
    float cy  = d.x * ah + acy;
    float cx  = d.y * aw + acx;
    float y1  = cy - 0.5f * h;
    float x1  = cx - 0.5f * w;
    g_boxes[i] = make_float4(y1, x1, y1 + h, x1 + w);
}

// ---------------------------------------------------------------------------
// Kernel 2: candidate-selection + smem-sort + greedy-scan NMS. 1 CTA / batch.
//   Equivalence: greedy NMS == visit boxes in (score desc, idx asc) order,
//   keep iff IoU < 0.5 vs all previously kept; stop at 300.
//   Tranches of score-buckets guarantee exactness if >TARGET boxes consumed.
// ---------------------------------------------------------------------------
__global__ __launch_bounds__(TPB, 1)
void nms_kernel(const float* __restrict__ labels) {
    extern __shared__ char dynsmem[];
    u64*    bufA    = (u64*)dynsmem;                  // 64 KB
    u64*    bufB    = (u64*)(dynsmem + 65536);        // 64 KB
    u32*    regionC = (u32*)(dynsmem + 131072);       // 64 KB: hist / radix counts
    float4* sChunk  = (float4*)(dynsmem + 131072);    // alias: chunk boxes (16 KB)

    __shared__ float4 sKept[TOPN];    // unclipped kept boxes
    __shared__ u32    sWarpSum[32];
    __shared__ int    sWarpCand[32];
    __shared__ int    sWinner;
    __shared__ int    sCnt;
    __shared__ int    sKlo, sKhi;

    const int b    = blockIdx.x;
    const int t    = threadIdx.x;
    const int lane = t & 31;
    const int warp = t >> 5;

    const float*  sc    = labels  + (size_t)b * NANCH;
    const float4* boxes = g_boxes + (size_t)b * NANCH;
    u32*          cum   = g_cum   + (size_t)b * NBUCK;

    // ---------------- phase 1: bucket histogram + prefix sums ----------------
    u32* hist = regionC;
    for (int i = t; i < NBUCK; i += TPB) hist[i] = 0u;
    __syncthreads();
    #pragma unroll
    for (int k = 0; k < SEG; k++) {
        u32 bits = ~__float_as_uint(sc[k * TPB + t]);
        atomicAdd(&hist[bits >> 19], 1u);        // top 13 bits: ascending = score desc
    }
    __syncthreads();

    {   // inclusive prefix over NBUCK buckets (8 per thread, contiguous)
        u32 loc[8], run = 0;
        #pragma unroll
        for (int i = 0; i < 8; i++) { run += hist[t * 8 + i]; loc[i] = run; }
        u32 excl = block_excl_scan(run, lane, warp, sWarpSum);
        #pragma unroll
        for (int i = 0; i < 8; i++) hist[t * 8 + i] = loc[i] + excl;
        __syncthreads();
        for (int i = t; i < NBUCK; i += TPB) cum[i] = hist[i];  // persist (regionC gets reused)
        __syncthreads();
    }

    // ---------------- tranche loop ----------------
    int kc   = 0;
    int curK = -1;
    u32 base = 0;

    while (kc < TOPN) {
        // --- choose K*: smallest j with >=TARGET candidates, capped at CAND_MAX ---
        if (t == 0) { sKlo = NBUCK; sKhi = NBUCK; }
        __syncthreads();
        for (int i = t; i < NBUCK; i += TPB) {
            if (i > curK) {
                u32 c = cum[i] - base;
                if (c >= (u32)TARGET)   atomicMin(&sKlo, i);
                if (c >  (u32)CAND_MAX) atomicMin(&sKhi, i);
            }
        }
        __syncthreads();
        int Kstar = min(sKlo, sKhi - 1);
        if (Kstar > NBUCK - 1) Kstar = NBUCK - 1;
        if (Kstar < curK + 1)  Kstar = curK + 1;   // pathological giant bucket (unreachable)

        // --- compact candidates (curK < bucket <= Kstar) into smem, unordered ---
        if (t == 0) sCnt = 0;
        __syncthreads();
        #pragma unroll
        for (int k = 0; k < SEG; k++) {
            int e = k * TPB + t;
            u32 bits = ~__float_as_uint(sc[e]);
            int kb = (int)(bits >> 19);
            if (kb > curK && kb <= Kstar) {
                int pos = atomicAdd(&sCnt, 1);
                if (pos < CAND_MAX) bufA[pos] = ((u64)bits << 16) | (u32)e;
            }
        }
        __syncthreads();
        int C = min(sCnt, CAND_MAX);
        for (int i = C + t; i < CAND_MAX; i += TPB) bufA[i] = ~0ull;  // pad to end
        __syncthreads();

        // --- 12-pass 4-bit LSD radix sort over 48-bit key, all in smem ---
        u32* counts = regionC;
        for (int p = 0; p < 12; p++) {
            u64* src = (p & 1) ? bufB : bufA;
            u64* dst = (p & 1) ? bufA : bufB;
            const int sh = 4 * p;

            #pragma unroll
            for (int i = 0; i < 16; i++) counts[t * 16 + i] = 0u;
            __syncthreads();

            u64 v[ITEMC];
            #pragma unroll
            for (int i = 0; i < ITEMC; i++) {
                v[i] = src[t * ITEMC + i];
                counts[(((u32)(v[i] >> sh)) & 15u) * TPB + t]++;
            }
            __syncthreads();

            u32 vv[16], run = 0;
            #pragma unroll
            for (int i = 0; i < 16; i++) { u32 x = counts[t * 16 + i]; vv[i] = run; run += x; }
            u32 excl = block_excl_scan(run, lane, warp, sWarpSum);
            #pragma unroll
            for (int i = 0; i < 16; i++) counts[t * 16 + i] = vv[i] + excl;
            __syncthreads();

            #pragma unroll
            for (int i = 0; i < ITEMC; i++) {
                u32 d = ((u32)(v[i] >> sh)) & 15u;
                u32 pos = counts[d * TPB + t]++;
                dst[pos] = v[i];
            }
            __syncthreads();
        }
        // 12 passes (even) -> sorted result in bufA

        // --- chunked greedy scan over sorted candidates ---
        for (int cb = 0; cb < C && kc < TOPN; cb += TPB) {
            int  pos  = cb + t;
            bool have = pos < C;
            u64  it   = have ? bufA[pos] : ~0ull;
            int  e    = (int)(it & 0xFFFFull);
            float4 myBox = make_float4(0.f, 0.f, 0.f, 0.f);
            if (have) myBox = boxes[e];
            sChunk[t] = myBox;                         // regionC free during scan
            bool alive = have;
            if (alive) {
                for (int j = 0; j < kc; j++)
                    if (iou_ref(sKept[j], myBox) >= 0.5f) { alive = false; break; }
            }
            __syncthreads();

            while (kc < TOPN) {
                u32 bal = __ballot_sync(0xFFFFFFFFu, alive);
                if (lane == 0) sWarpCand[warp] = bal ? (warp * 32 + __ffs(bal) - 1) : 0x7FFFFFFF;
                __syncthreads();
                if (t < 32) {
                    int c = sWarpCand[t];
                    #pragma unroll
                    for (int off = 16; off > 0; off >>= 1)
                        c = min(c, __shfl_down_sync(0xFFFFFFFFu, c, off));
                    if (t == 0) sWinner = c;
                }
                __syncthreads();
                int w = sWinner;
                if (w == 0x7FFFFFFF) break;            // chunk exhausted

                float4 wb = sChunk[w];
                if (t == 0) {
                    sKept[kc] = wb;                    // unclipped, for suppression
                    float4 c;
                    c.x = fminf(fmaxf(wb.x, 0.0f), 1.0f);
                    c.y = fminf(fmaxf(wb.y, 0.0f), 1.0f);
                    c.z = fminf(fmaxf(wb.z, 0.0f), 1.0f);
                    c.w = fminf(fmaxf(wb.w, 0.0f), 1.0f);
                    g_nms[b * TOPN + kc] = c;
                }
                if (alive) {
                    if (t == w)                          alive = false;  // explicit self-suppress
                    else if (iou_ref(wb, myBox) >= 0.5f) alive = false;
                }
                kc++;
                __syncthreads();
            }
        }

        // --- next tranche (exact refill) ---
        if (Kstar >= NBUCK - 1) break;                 // all boxes consumed
        curK = Kstar;
        base = cum[Kstar];
        __syncthreads();
    }

    // zero-fill remaining (invalid) slots
    for (int s = kc + t; s < TOPN; s += TPB)
        g_nms[b * TOPN + s] = make_float4(0.f, 0.f, 0.f, 0.f);
}

// ---------------------------------------------------------------------------
// Kernel 3: IoU vs GT, per-row max/argmax, stable rank-by-counting, write out.
// ---------------------------------------------------------------------------
__global__ void select_kernel(const float4* __restrict__ gt,
                              float* __restrict__ out,
                              int out_size) {
    __shared__ float4 nb[TOPN];
    __shared__ float4 gtb[NGT];
    __shared__ float  merged[TOPN];
    __shared__ int    gbest[TOPN];

    const int b = blockIdx.x;
    const int t = threadIdx.x;   // 512 threads

    if (t < TOPN) nb[t] = g_nms[b * TOPN + t];
    int u = t - TOPN;
    if (u >= 0 && u < NGT) gtb[u] = gt[b * NGT + u];
    __syncthreads();

    if (t < TOPN) {
        float4 A = nb[t];
        float areaA = (A.z - A.x) * (A.w - A.y);
        float best = -INFINITY; int bj = 0;
        #pragma unroll 4
        for (int j = 0; j < NGT; j++) {
            float4 G = gtb[j];
            float yy1 = fmaxf(A.x, G.x);
            float xx1 = fmaxf(A.y, G.y);
            float yy2 = fminf(A.z, G.z);
            float xx2 = fminf(A.w, G.w);
            float ih  = fmaxf(yy2 - yy1, 0.0f);
            float iw  = fmaxf(xx2 - xx1, 0.0f);
            float inter = ih * iw;
            float areaG = (G.z - G.x) * (G.w - G.y);
            float iou   = inter / (((areaA + areaG) - inter) + 1e-7f);
            if (iou > best) { best = iou; bj = j; }   // strict > == first occurrence
        }
        merged[t] = best;
        gbest[t]  = bj;
    }
    __syncthreads();

    if (t < TOPN) {
        float mv = merged[t];
        int rank = 0;
        for (int q = 0; q < TOPN; q++) {
            float qv = merged[q];
            rank += (qv > mv) || (qv == mv && q < t);   // stable: matches jnp.argsort
        }
        if (rank < NPOS) {
            float4 A = nb[t];
            float* o = out + (size_t)b * 512 + (size_t)rank * 4;
            o[0] = A.x; o[1] = A.y; o[2] = A.z; o[3] = A.w;
            if (out_size >= BATCH * 512 + BATCH * NGT) {
                out[BATCH * 512 + b * NGT + rank] = (float)gbest[t];
            }
        }
    }

    // negatives: rows 64..127 are zeros
    for (int i = t; i < 256; i += blockDim.x)
        out[(size_t)b * 512 + 256 + i] = 0.0f;
}

// ---------------------------------------------------------------------------
extern "C" void kernel_launch(void* const* d_in, const int* in_sizes, int n_in,
                              void* d_out, int out_size) {
    const float4* deltas  = (const float4*)d_in[0];  // (B,64,64,36)
    const float*  labels  = (const float*)d_in[1];   // (B,64,64,9)
    const float4* anchors = (const float4*)d_in[2];  // (B,N,4)
    const float4* gt      = (const float4*)d_in[3];  // (B,64,4)
    float* out = (float*)d_out;

    (void)in_sizes; (void)n_in;

    static_assert(SEG * TPB == NANCH, "tiling must cover N exactly");
    static_assert(ITEMC * TPB == CAND_MAX, "candidate tiling");

    size_t smem = 196608;   // bufA(64K) + bufB(64K) + regionC(64K)
    cudaFuncSetAttribute(nms_kernel, cudaFuncAttributeMaxDynamicSharedMemorySize, (int)smem);

    decode_kernel<<<(BATCH * NANCH + 255) / 256, 256>>>(deltas, anchors);
    nms_kernel<<<BATCH, TPB, smem>>>(labels);
    select_kernel<<<BATCH, 512>>>(gt, out, out_size);
}

// round 6
// speedup vs baseline: 17.9345x; 1.1524x over previous
#include <cuda_runtime.h>
#include <math.h>

// Problem constants (fixed by the reference setup)
#define BATCH    16
#define NANCH    36864      // 64*64*9
#define TPB      1024
#define SEG      36         // NANCH / TPB
#define TOPN     300
#define NGT      64
#define NPOS     64
#define NBUCK    8192       // top-13-bit score buckets
#define CAND_MAX 8192       // max candidates per tranche (smem capacity)
#define ITEMC    8          // CAND_MAX / TPB
#define TARGET   4096       // desired candidates in first tranche

typedef unsigned long long u64;
typedef unsigned int u32;

// Scratch (static device allocations — no runtime alloc)
__device__ float4 g_boxes[BATCH * NANCH];   // decoded (unclipped) boxes
__device__ u32    g_cum[BATCH * NBUCK];     // inclusive bucket prefix sums

// ---------------------------------------------------------------------------
// IoU exactly as reference: inter / (((areaA + areaB) - inter) + 1e-7)
// ---------------------------------------------------------------------------
__device__ __forceinline__ float iou_ref(float4 a, float4 b) {
    float yy1 = fmaxf(a.x, b.x);
    float xx1 = fmaxf(a.y, b.y);
    float yy2 = fminf(a.z, b.z);
    float xx2 = fminf(a.w, b.w);
    float ih  = fmaxf(yy2 - yy1, 0.0f);
    float iw  = fmaxf(xx2 - xx1, 0.0f);
    float inter = ih * iw;
    float areaA = (a.z - a.x) * (a.w - a.y);
    float areaB = (b.z - b.x) * (b.w - b.y);
    return inter / (((areaA + areaB) - inter) + 1e-7f);
}

// exclusive block scan of per-thread totals (1024 threads, 32 warps).
// After return (and until the next call), sWarpSum[31] holds the grand total.
__device__ __forceinline__ u32 block_excl_scan(u32 run, int lane, int warp, u32* sWarpSum) {
    u32 x = run;
    #pragma unroll
    for (int off = 1; off < 32; off <<= 1) {
        u32 y = __shfl_up_sync(0xFFFFFFFFu, x, off);
        if (lane >= off) x += y;
    }
    if (lane == 31) sWarpSum[warp] = x;
    __syncthreads();
    if (warp == 0) {
        u32 s = sWarpSum[lane];
        #pragma unroll
        for (int off = 1; off < 32; off <<= 1) {
            u32 y = __shfl_up_sync(0xFFFFFFFFu, s, off);
            if (lane >= off) s += y;
        }
        sWarpSum[lane] = s;
    }
    __syncthreads();
    u32 warpOff = (warp == 0) ? 0u : sWarpSum[warp - 1];
    return warpOff + x - run;
}

// ---------------------------------------------------------------------------
// Kernel 1: decode deltas -> boxes (mirrors reference op order exactly)
// ---------------------------------------------------------------------------
__global__ void decode_kernel(const float4* __restrict__ deltas,
                              const float4* __restrict__ anchors) {
    int i = blockIdx.x * blockDim.x + threadIdx.x;
    if (i >= BATCH * NANCH) return;
    float4 a = anchors[i];
    float4 d = deltas[i];
    float ah  = a.z - a.x;
    float aw  = a.w - a.y;
    float acy = a.x + 0.5f * ah;
    float acx = a.y + 0.5f * aw;
    float h   = expf(d.z) * ah;
    float w   = expf(d.w) * aw;
    float cy  = d.x * ah + acy;
    float cx  = d.y * aw + acx;
    float y1  = cy - 0.5f * h;
    float x1  = cx - 0.5f * w;
    g_boxes[i] = make_float4(y1, x1, y1 + h, x1 + w);
}

// ---------------------------------------------------------------------------
// Kernel 2 (fused): histogram -> tranche compact -> smem radix sort ->
// warp-window greedy scan -> RoI selection + output. One CTA per batch.
// ---------------------------------------------------------------------------
__global__ __launch_bounds__(TPB, 1)
void nms_kernel(const float* __restrict__ labels,
                const float4* __restrict__ gt,
                float* __restrict__ out,
                int out_size) {
    extern __shared__ char dynsmem[];
    u64* bufA    = (u64*)dynsmem;                  // 64 KB
    u64* bufB    = (u64*)(dynsmem + 65536);        // 64 KB
    u32* regionC = (u32*)(dynsmem + 131072);       // 64 KB: hist / radix counts / select scratch

    __shared__ float4 sKept[TOPN];    // unclipped kept boxes (for suppression)
    __shared__ float4 sNms[TOPN];     // clipped kept boxes  (NMS output)
    __shared__ float4 sGtb[NGT];
    __shared__ u32    sWarpSum[32];
    __shared__ int    sKc;
    __shared__ int    sKlo, sKhi;

    const int b    = blockIdx.x;
    const int t    = threadIdx.x;
    const int lane = t & 31;
    const int warp = t >> 5;

    const float*  sc    = labels  + (size_t)b * NANCH;
    const float4* boxes = g_boxes + (size_t)b * NANCH;
    u32*          cum   = g_cum   + (size_t)b * NBUCK;

    // ---------------- phase 1: bucket histogram + prefix sums ----------------
    u32* hist = regionC;
    for (int i = t; i < NBUCK; i += TPB) hist[i] = 0u;
    __syncthreads();
    #pragma unroll
    for (int k = 0; k < SEG; k++) {
        u32 bits = ~__float_as_uint(sc[k * TPB + t]);   // coalesced
        atomicAdd(&hist[bits >> 19], 1u);               // ascending bucket = score desc
    }
    __syncthreads();
    {   // inclusive prefix over NBUCK buckets
        u32 loc[8], run = 0;
        #pragma unroll
        for (int i = 0; i < 8; i++) { run += hist[t * 8 + i]; loc[i] = run; }
        u32 excl = block_excl_scan(run, lane, warp, sWarpSum);
        #pragma unroll
        for (int i = 0; i < 8; i++) hist[t * 8 + i] = loc[i] + excl;
        __syncthreads();
        for (int i = t; i < NBUCK; i += TPB) cum[i] = hist[i];  // persist (regionC reused)
        __syncthreads();
    }

    // ---------------- tranche loop ----------------
    int kc   = 0;
    int curK = -1;
    u32 base = 0;

    while (kc < TOPN) {
        // --- choose K*: smallest j with >=TARGET candidates, capped at CAND_MAX ---
        if (t == 0) { sKlo = NBUCK; sKhi = NBUCK; }
        __syncthreads();
        for (int i = t; i < NBUCK; i += TPB) {
            if (i > curK) {
                u32 c = cum[i] - base;
                if (c >= (u32)TARGET)   atomicMin(&sKlo, i);
                if (c >  (u32)CAND_MAX) atomicMin(&sKhi, i);
            }
        }
        __syncthreads();
        int Kstar = min(sKlo, sKhi - 1);
        if (Kstar > NBUCK - 1) Kstar = NBUCK - 1;
        if (Kstar < curK + 1)  Kstar = curK + 1;   // pathological giant bucket (unreachable)

        // --- deterministic compact in ascending-idx order (thread t owns [t*SEG, t*SEG+SEG)) ---
        int myCnt = 0;
        #pragma unroll
        for (int i = 0; i < SEG; i++) {
            u32 bits = ~__float_as_uint(sc[t * SEG + i]);
            int kb = (int)(bits >> 19);
            myCnt += (kb > curK && kb <= Kstar) ? 1 : 0;
        }
        u32 off = block_excl_scan((u32)myCnt, lane, warp, sWarpSum);
        int total = (int)sWarpSum[31];
        #pragma unroll
        for (int i = 0; i < SEG; i++) {
            int e = t * SEG + i;
            u32 bits = ~__float_as_uint(sc[e]);
            int kb = (int)(bits >> 19);
            if (kb > curK && kb <= Kstar) {
                if (off < (u32)CAND_MAX) bufA[off] = ((u64)bits << 16) | (u32)e;
                off++;
            }
        }
        __syncthreads();
        int C = min(total, CAND_MAX);
        for (int i = C + t; i < CAND_MAX; i += TPB) bufA[i] = ~0ull;
        __syncthreads();

        // --- 8-pass 4-bit LSD radix over the 32 score bits (bits 16..47).
        //     Initial order is idx-ascending, stability resolves score ties. ---
        u32* counts = regionC;
        for (int p = 0; p < 8; p++) {
            u64* src = (p & 1) ? bufB : bufA;
            u64* dst = (p & 1) ? bufA : bufB;
            const int sh = 16 + 4 * p;

            #pragma unroll
            for (int i = 0; i < 16; i++) counts[t * 16 + i] = 0u;
            __syncthreads();

            u64 v[ITEMC];
            #pragma unroll
            for (int i = 0; i < ITEMC; i++) {
                v[i] = src[t * ITEMC + i];
                counts[(((u32)(v[i] >> sh)) & 15u) * TPB + t]++;   // bank = t%32: conflict-free
            }
            __syncthreads();

            u32 vv[16], run = 0;
            #pragma unroll
            for (int i = 0; i < 16; i++) { u32 x = counts[t * 16 + i]; vv[i] = run; run += x; }
            u32 excl = block_excl_scan(run, lane, warp, sWarpSum);
            #pragma unroll
            for (int i = 0; i < 16; i++) counts[t * 16 + i] = vv[i] + excl;
            __syncthreads();

            #pragma unroll
            for (int i = 0; i < ITEMC; i++) {
                u32 d = ((u32)(v[i] >> sh)) & 15u;
                u32 pos = counts[d * TPB + t]++;
                dst[pos] = v[i];
            }
            __syncthreads();
        }
        // 8 passes (even) -> sorted result in bufA: (score desc, idx asc)

        // --- warp-window greedy scan: 1 block barrier per 32 candidates ---
        for (int cb = 0; cb < C && kc < TOPN; cb += TPB) {
            int  pos  = cb + t;
            bool have = pos < C;
            u64  it   = have ? bufA[pos] : ~0ull;
            int  e    = (int)(it & 0xFFFFull);
            float4 myBox = make_float4(0.f, 0.f, 0.f, 0.f);
            if (have) myBox = boxes[e];
            bool alive = have;
            if (alive) {
                for (int j = 0; j < kc; j++)
                    if (iou_ref(sKept[j], myBox) >= 0.5f) { alive = false; break; }
            }
            __syncthreads();   // sKept stable + alive computed before windows start

            for (int w = 0; w < 32 && kc < TOPN; w++) {
                if (warp == w) {
                    // intra-warp serial greedy over this window (sorted order)
                    u32 m = __ballot_sync(0xFFFFFFFFu, alive);
                    int kloc = kc;
                    while (m && kloc < TOPN) {
                        int win = __ffs((int)m) - 1;
                        float4 wb;
                        wb.x = __shfl_sync(0xFFFFFFFFu, myBox.x, win);
                        wb.y = __shfl_sync(0xFFFFFFFFu, myBox.y, win);
                        wb.z = __shfl_sync(0xFFFFFFFFu, myBox.z, win);
                        wb.w = __shfl_sync(0xFFFFFFFFu, myBox.w, win);
                        if (lane == win) {
                            sKept[kloc] = myBox;          // unclipped for suppression
                            float4 c;
                            c.x = fminf(fmaxf(myBox.x, 0.0f), 1.0f);
                            c.y = fminf(fmaxf(myBox.y, 0.0f), 1.0f);
                            c.z = fminf(fmaxf(myBox.z, 0.0f), 1.0f);
                            c.w = fminf(fmaxf(myBox.w, 0.0f), 1.0f);
                            sNms[kloc] = c;
                            alive = false;                 // explicit self-suppress
                        } else if (alive && iou_ref(wb, myBox) >= 0.5f) {
                            alive = false;
                        }
                        kloc++;
                        m = __ballot_sync(0xFFFFFFFFu, alive);
                    }
                    if (lane == 0) sKc = kloc;
                }
                __syncthreads();                           // publish sKept[kc..nk), sKc
                int nk = sKc;
                if (warp > w && alive) {                   // later windows: self-suppress vs new kept
                    for (int j = kc; j < nk; j++)
                        if (iou_ref(sKept[j], myBox) >= 0.5f) { alive = false; break; }
                }
                kc = nk;
            }
        }

        // --- next tranche (exact refill) ---
        if (Kstar >= NBUCK - 1) break;                     // all boxes consumed
        curK = Kstar;
        base = cum[Kstar];
        __syncthreads();
    }

    // zero-fill remaining (invalid) NMS slots
    for (int s = kc + t; s < TOPN; s += TPB)
        sNms[s] = make_float4(0.f, 0.f, 0.f, 0.f);

    // ---------------- fused RoI selection (former select_kernel) ----------------
    float* merged = (float*)regionC;           // TOPN floats
    int*   gbest  = (int*)(regionC + 512);     // TOPN ints

    if (t < NGT) sGtb[t] = gt[b * NGT + t];
    __syncthreads();

    if (t < TOPN) {
        float4 A = sNms[t];
        float areaA = (A.z - A.x) * (A.w - A.y);
        float best = -INFINITY; int bj = 0;
        #pragma unroll 4
        for (int j = 0; j < NGT; j++) {
            float4 G = sGtb[j];
            float yy1 = fmaxf(A.x, G.x);
            float xx1 = fmaxf(A.y, G.y);
            float yy2 = fminf(A.z, G.z);
            float xx2 = fminf(A.w, G.w);
            float ih  = fmaxf(yy2 - yy1, 0.0f);
            float iw  = fmaxf(xx2 - xx1, 0.0f);
            float inter = ih * iw;
            float areaG = (G.z - G.x) * (G.w - G.y);
            float iou   = inter / (((areaA + areaG) - inter) + 1e-7f);
            if (iou > best) { best = iou; bj = j; }   // strict > == first occurrence
        }
        merged[t] = best;
        gbest[t]  = bj;
    }
    __syncthreads();

    if (t < TOPN) {
        float mv = merged[t];
        int rank = 0;
        for (int q = 0; q < TOPN; q++) {
            float qv = merged[q];
            rank += (qv > mv) || (qv == mv && q < t);   // stable: matches jnp.argsort
        }
        if (rank < NPOS) {
            float4 A = sNms[t];
            float* o = out + (size_t)b * 512 + (size_t)rank * 4;
            o[0] = A.x; o[1] = A.y; o[2] = A.z; o[3] = A.w;
            if (out_size >= BATCH * 512 + BATCH * NGT) {
                out[BATCH * 512 + b * NGT + rank] = (float)gbest[t];
            }
        }
    }

    // negatives: rows 64..127 are zeros
    for (int i = t; i < 256; i += TPB)
        out[(size_t)b * 512 + 256 + i] = 0.0f;
}

// ---------------------------------------------------------------------------
extern "C" void kernel_launch(void* const* d_in, const int* in_sizes, int n_in,
                              void* d_out, int out_size) {
    const float4* deltas  = (const float4*)d_in[0];  // (B,64,64,36)
    const float*  labels  = (const float*)d_in[1];   // (B,64,64,9)
    const float4* anchors = (const float4*)d_in[2];  // (B,N,4)
    const float4* gt      = (const float4*)d_in[3];  // (B,64,4)
    float* out = (float*)d_out;

    (void)in_sizes; (void)n_in;

    static_assert(SEG * TPB == NANCH, "tiling must cover N exactly");
    static_assert(ITEMC * TPB == CAND_MAX, "candidate tiling");

    size_t smem = 196608;   // bufA(64K) + bufB(64K) + regionC(64K)
    cudaFuncSetAttribute(nms_kernel, cudaFuncAttributeMaxDynamicSharedMemorySize, (int)smem);

    decode_kernel<<<(BATCH * NANCH + 255) / 256, 256>>>(deltas, anchors);
    nms_kernel<<<BATCH, TPB, smem>>>(labels, gt, out, out_size);
}